// round 1
// baseline (speedup 1.0000x reference)
#include <cuda_runtime.h>
#include <math.h>

// Problem constants
#define BB   256           // batch
#define KIN  8             // in_units (reduction sub-dim)
#define CC   1152          // in_channels (capsules in)
#define JJ   10            // num_units
#define DD   16            // unit_size
#define JD   160           // JJ*DD
#define KC   (KIN*CC)      // 9216 total reduction dim

#define CCHUNK 16          // capsules per reduction chunk
#define NCHUNK (CC/CCHUNK) // 72
#define RTILE  (CCHUNK*KIN)// 128 reduction rows per chunk
#define BTILE  128         // batch rows per block
#define NBT    (BB/BTILE)  // 2

// ---------------------------------------------------------------------------
// Scratch (device globals; no runtime allocation allowed)
// ---------------------------------------------------------------------------
__device__ float g_P[KIN * CC * JD];          // P[k][c][jd] = c_ij[c][j] * W[c,j,d,k]
__device__ float g_spart[NCHUNK * BB * JD];   // split-K partials of s
__device__ float g_v[BB * JD];                // v[b][jd]
__device__ float g_b[CC * JJ];                // routing logits b_ij

// ---------------------------------------------------------------------------
// Kernel A: per-capsule softmax over J and build P[k][c][jd]
// grid = CC blocks, block = 160 threads (one per jd)
// ---------------------------------------------------------------------------
__global__ void __launch_bounds__(JD) kernA(const float* __restrict__ W) {
    int c = blockIdx.x;
    int t = threadIdx.x;      // jd = j*16 + d
    int j = t >> 4;

    float bv[JJ];
    float mx = -1e30f;
#pragma unroll
    for (int q = 0; q < JJ; q++) { bv[q] = g_b[c * JJ + q]; mx = fmaxf(mx, bv[q]); }
    float sum = 0.f;
#pragma unroll
    for (int q = 0; q < JJ; q++) { bv[q] = expf(bv[q] - mx); sum += bv[q]; }
    float cij = bv[j] / sum;

    // W[c,j,d,k] flat = c*1280 + (j*16+d)*8 + k = c*1280 + t*8 + k
    const float* wr = W + (size_t)c * (JJ * DD * KIN) + (size_t)t * KIN;
#pragma unroll
    for (int k = 0; k < KIN; k++)
        g_P[((size_t)k * CC + c) * JD + t] = cij * wr[k];
}

// ---------------------------------------------------------------------------
// Kernel B: GEMM1  s_partial[chunk][b][jd] = sum over chunk's (k,c) of x * P
// grid = (NCHUNK, NBT), block = 256
// smem: Xs[r][129] (pad for conflict-free), Ps[r][160]
// ---------------------------------------------------------------------------
__global__ void __launch_bounds__(256, 1) kernB(const float* __restrict__ x) {
    extern __shared__ float sm[];
    float* Xs = sm;                 // RTILE * 129
    float* Ps = sm + RTILE * 129;   // RTILE * 160

    int chunk = blockIdx.x;
    int c0 = chunk * CCHUNK;
    int b0 = blockIdx.y * BTILE;
    int tid = threadIdx.x;

    // Load P tile: local row r = k*16 + cl  <->  global row (k*CC + c0 + cl)
    for (int i = tid; i < RTILE * JD / 4; i += 256) {
        int r = i / 40, q4 = i % 40;
        int k = r >> 4, cl = r & 15;
        reinterpret_cast<float4*>(Ps)[i] =
            *reinterpret_cast<const float4*>(g_P + ((size_t)k * CC + c0 + cl) * JD + q4 * 4);
    }
    // Load X tile: Xs[r][b], r = k*16 + cl ; x flat = b*9216 + k*1152 + c
    for (int i = tid; i < BTILE * RTILE / 4; i += 256) {
        int b  = i >> 5;
        int rq = i & 31;
        int k = rq >> 2, clq = (rq & 3) * 4;
        float4 xv = *reinterpret_cast<const float4*>(
            x + (size_t)(b0 + b) * (KIN * CC) + (size_t)k * CC + c0 + clq);
        int rb = k * 16 + clq;
        Xs[(rb + 0) * 129 + b] = xv.x;
        Xs[(rb + 1) * 129 + b] = xv.y;
        Xs[(rb + 2) * 129 + b] = xv.z;
        Xs[(rb + 3) * 129 + b] = xv.w;
    }
    __syncthreads();

    int tx = tid & 15, ty = tid >> 4;   // tx -> 10 jd cols, ty -> 8 b rows
    float acc[8][10];
#pragma unroll
    for (int a = 0; a < 8; a++)
#pragma unroll
        for (int e = 0; e < 10; e++) acc[a][e] = 0.f;

#pragma unroll 2
    for (int r = 0; r < RTILE; r++) {
        float xv[8], pv[10];
#pragma unroll
        for (int a = 0; a < 8; a++)  xv[a] = Xs[r * 129 + ty * 8 + a];
#pragma unroll
        for (int e = 0; e < 10; e++) pv[e] = Ps[r * JD + tx * 10 + e];
#pragma unroll
        for (int a = 0; a < 8; a++)
#pragma unroll
            for (int e = 0; e < 10; e++) acc[a][e] = fmaf(xv[a], pv[e], acc[a][e]);
    }
    __syncthreads();

    // Stage output tile in smem (reuse Ps), then coalesced float4 store
    float* Os = Ps;
#pragma unroll
    for (int a = 0; a < 8; a++)
#pragma unroll
        for (int e = 0; e < 10; e++)
            Os[(ty * 8 + a) * JD + tx * 10 + e] = acc[a][e];
    __syncthreads();

    float* dst = g_spart + (size_t)chunk * (BB * JD) + (size_t)b0 * JD;
    for (int i = tid; i < BTILE * JD / 4; i += 256)
        reinterpret_cast<float4*>(dst)[i] = reinterpret_cast<const float4*>(Os)[i];
}

// ---------------------------------------------------------------------------
// Kernel C: reduce split-K partials + squash -> v ; optionally write d_out
// grid = BB blocks, block = 160 threads
// ---------------------------------------------------------------------------
__global__ void __launch_bounds__(JD) kernC(float* __restrict__ out) {
    int b = blockIdx.x, t = threadIdx.x;
    float s = 1e-5f;                        // ref adds 1e-5 BEFORE magnitudes
    const float* sp = g_spart + (size_t)b * JD + t;
#pragma unroll 8
    for (int ch = 0; ch < NCHUNK; ch++)
        s += sp[(size_t)ch * (BB * JD)];

    __shared__ float sv[JD];
    sv[t] = s;
    __syncthreads();

    int j = t >> 4;
    float mag = 0.f;
#pragma unroll
    for (int d2 = 0; d2 < DD; d2++) { float u = sv[j * 16 + d2]; mag += u * u; }
    float v = s * (mag / ((1.f + mag) * sqrtf(mag)));

    g_v[(size_t)b * JD + t] = v;
    if (out) out[(size_t)b * JD + t] = v;   // out shape (B,J,D,1) is same linearization
}

// ---------------------------------------------------------------------------
// Kernel D: GEMM2  G[(k,c),(j,d)] = sum_b x[b,k,c] v[b,j,d]  (per b-half),
// then contract with W into agreement and atomically update b_ij.
// grid = (NCHUNK, NBT), block = 256
// smem: Xs[b][128], Vs[b][160] (Vs reused as G tile in epilogue)
// ---------------------------------------------------------------------------
__global__ void __launch_bounds__(256, 1) kernD(const float* __restrict__ x,
                                                const float* __restrict__ W) {
    extern __shared__ float sm[];
    float* Xs = sm;                    // BTILE * RTILE
    float* Vs = sm + BTILE * RTILE;    // BTILE * JD

    int chunk = blockIdx.x;
    int c0 = chunk * CCHUNK;
    int b0 = blockIdx.y * BTILE;
    int tid = threadIdx.x;

    // Load V tile (contiguous)
    for (int i = tid; i < BTILE * JD / 4; i += 256)
        reinterpret_cast<float4*>(Vs)[i] =
            *reinterpret_cast<const float4*>(g_v + (size_t)b0 * JD + i * 4);
    // Load X tile: Xs[b][r]
    for (int i = tid; i < BTILE * RTILE / 4; i += 256) {
        int b  = i >> 5;
        int rq = i & 31;
        int k = rq >> 2, clq = (rq & 3) * 4;
        float4 xv = *reinterpret_cast<const float4*>(
            x + (size_t)(b0 + b) * (KIN * CC) + (size_t)k * CC + c0 + clq);
        int rb = k * 16 + clq;
        Xs[b * RTILE + rb + 0] = xv.x;
        Xs[b * RTILE + rb + 1] = xv.y;
        Xs[b * RTILE + rb + 2] = xv.z;
        Xs[b * RTILE + rb + 3] = xv.w;
    }
    __syncthreads();

    int tx = tid & 15, ty = tid >> 4;   // tx -> 10 jd cols, ty -> 8 r rows
    float acc[8][10];
#pragma unroll
    for (int a = 0; a < 8; a++)
#pragma unroll
        for (int e = 0; e < 10; e++) acc[a][e] = 0.f;

#pragma unroll 2
    for (int b = 0; b < BTILE; b++) {
        float xv[8], vv[10];
#pragma unroll
        for (int a = 0; a < 8; a++)  xv[a] = Xs[b * RTILE + ty * 8 + a];
#pragma unroll
        for (int e = 0; e < 10; e++) vv[e] = Vs[b * JD + tx * 10 + e];
#pragma unroll
        for (int a = 0; a < 8; a++)
#pragma unroll
            for (int e = 0; e < 10; e++) acc[a][e] = fmaf(xv[a], vv[e], acc[a][e]);
    }
    __syncthreads();

    // Park G tile in smem (reuse Vs region)
    float* Gs = Vs;
#pragma unroll
    for (int a = 0; a < 8; a++)
#pragma unroll
        for (int e = 0; e < 10; e++)
            Gs[(ty * 8 + a) * JD + tx * 10 + e] = acc[a][e];
    __syncthreads();

    // agreement[c,j] = sum_{d,k} W[c,j,d,k] * G[(k,c),(j,d)]
    if (tid < CCHUNK * JJ) {
        int cl = tid / JJ, j = tid % JJ;
        int c = c0 + cl;
        const float* wr = W + (size_t)c * (JJ * DD * KIN) + (size_t)j * (DD * KIN);
        float ag = 0.f;
#pragma unroll
        for (int d2 = 0; d2 < DD; d2++)
#pragma unroll
            for (int k = 0; k < KIN; k++)
                ag = fmaf(wr[d2 * KIN + k], Gs[(k * 16 + cl) * JD + j * 16 + d2], ag);
        atomicAdd(&g_b[c * JJ + j], ag);
    }
}

// ---------------------------------------------------------------------------
// Host launcher (graph-capturable: kernels + one memset, no alloc/sync)
// ---------------------------------------------------------------------------
extern "C" void kernel_launch(void* const* d_in, const int* in_sizes, int n_in,
                              void* d_out, int out_size) {
    const float* x = (const float*)d_in[0];
    const float* W = (const float*)d_in[1];
    if (in_sizes[0] != BB * KIN * CC) {  // defensive: map by element count
        x = (const float*)d_in[1];
        W = (const float*)d_in[0];
    }

    const int SMEM_B = (RTILE * 129 + RTILE * JD) * 4;    // 147968
    const int SMEM_D = (BTILE * RTILE + BTILE * JD) * 4;  // 147456
    cudaFuncSetAttribute(kernB, cudaFuncAttributeMaxDynamicSharedMemorySize, SMEM_B);
    cudaFuncSetAttribute(kernD, cudaFuncAttributeMaxDynamicSharedMemorySize, SMEM_D);

    void* pb = nullptr;
    cudaGetSymbolAddress(&pb, g_b);
    cudaMemsetAsync(pb, 0, CC * JJ * sizeof(float));      // b_ij = 0 every call

    dim3 gG(NCHUNK, NBT);
    for (int it = 0; it < 4; it++) {
        kernA<<<CC, JD>>>(W);                              // softmax + build P
        kernB<<<gG, 256, SMEM_B>>>(x);                     // s partials
        kernC<<<BB, JD>>>(it == 3 ? (float*)d_out : nullptr); // reduce + squash
        if (it < 3)                                        // iter-4 agreement is dead
            kernD<<<gG, 256, SMEM_D>>>(x, W);              // G + agreement -> b_ij
    }
}

// round 2
// speedup vs baseline: 1.5912x; 1.5912x over previous
#include <cuda_runtime.h>
#include <math.h>

// Problem constants
#define BB   256           // batch
#define KIN  8             // in_units
#define CC   1152          // in_channels
#define JJ   10            // num_units
#define DD   16            // unit_size
#define JD   160           // JJ*DD

#define CCHUNK 16          // capsules per chunk
#define NCHUNK (CC/CCHUNK) // 72
#define RTILE  (CCHUNK*KIN)// 128 reduction rows per chunk
#define BTILE  128         // batch rows per block
#define NBT    (BB/BTILE)  // 2
#define XSTR   132         // padded stride (16B-aligned rows, conflict-free)

typedef unsigned long long ull;

// ---------------------------------------------------------------------------
// Scratch (device globals; runtime allocation forbidden)
// ---------------------------------------------------------------------------
__device__ float g_spart[NCHUNK * BB * JD];   // split-K partials of s
__device__ float g_v[BB * JD];                // v[b][jd]
__device__ float g_b[CC * JJ];                // routing logits

__device__ __forceinline__ ull pack2(float x) {
    ull r; asm("mov.b64 %0, {%1, %1};" : "=l"(r) : "f"(x)); return r;
}
__device__ __forceinline__ void fma2(ull& d, ull a, ull b) {
    asm("fma.rn.f32x2 %0, %1, %2, %0;" : "+l"(d) : "l"(a), "l"(b));
}

// ---------------------------------------------------------------------------
// Kernel B (fused softmax + GEMM1):
//   s_partial[chunk][b][jd] = sum over chunk's (k,c) of x[b,k,c] * cij[c,j] * W[c,j,d,k]
// grid = (NCHUNK, NBT), block = 256
// smem: Xs[r][XSTR] transposed X, Ps[r][160] scaled-W, cs[160] softmax
// ---------------------------------------------------------------------------
__global__ void __launch_bounds__(256, 1) kernB(const float* __restrict__ x,
                                                const float* __restrict__ W) {
    extern __shared__ float sm[];
    float* Xs = sm;                           // RTILE * XSTR   [r][b]
    float* Ps = sm + RTILE * XSTR;            // RTILE * JD     [r][jd]
    float* cs = sm + RTILE * XSTR + RTILE * JD; // CCHUNK*JJ = 160

    int chunk = blockIdx.x;
    int c0 = chunk * CCHUNK;
    int b0 = blockIdx.y * BTILE;
    int tid = threadIdx.x;

    // --- per-capsule softmax over J for this chunk's 16 capsules ---
    if (tid < CCHUNK * JJ) {
        int cl = tid / JJ, j = tid - cl * JJ;
        const float* br = g_b + (size_t)(c0 + cl) * JJ;
        float bv[JJ], mx = -1e30f;
#pragma unroll
        for (int q = 0; q < JJ; q++) { bv[q] = br[q]; mx = fmaxf(mx, bv[q]); }
        float sum = 0.f;
#pragma unroll
        for (int q = 0; q < JJ; q++) { bv[q] = expf(bv[q] - mx); sum += bv[q]; }
        cs[tid] = bv[j] / sum;
    }

    // --- X tile, transposed to [r][b], conflict-free STS.128 ---
    // i -> (r = i & 127, bq = i >> 7); gather 4 b-values (stride 9216 floats)
    for (int i = tid; i < RTILE * BTILE / 4; i += 256) {
        int r = i & 127, bq = i >> 7;
        int k = r >> 4, cl = r & 15;
        const float* xp = x + (size_t)(b0 + bq * 4) * (KIN * CC) + k * CC + c0 + cl;
        float4 v;
        v.x = xp[0];
        v.y = xp[KIN * CC];
        v.z = xp[2 * KIN * CC];
        v.w = xp[3 * KIN * CC];
        *reinterpret_cast<float4*>(Xs + r * XSTR + bq * 4) = v;
    }
    __syncthreads();   // cs ready before scaling W

    // --- P tile: Ps[k*16+cl][j*16+d] = cs[cl][j] * W[c0+cl, j, d, k] ---
    // W float4 covers 4 consecutive k for fixed (c,j,d)
    for (int i = tid; i < RTILE * JD / 4; i += 256) {
        int cl = i / 320, rem = i - cl * 320;
        int jd = rem >> 1, k4 = rem & 1;       // k4*4 .. k4*4+3
        float scale = cs[cl * JJ + (jd >> 4)];
        float4 wv = *reinterpret_cast<const float4*>(
            W + (size_t)(c0 + cl) * (JJ * DD * KIN) + (size_t)jd * KIN + k4 * 4);
        int kb = k4 * 4;
        Ps[((kb + 0) * 16 + cl) * JD + jd] = scale * wv.x;
        Ps[((kb + 1) * 16 + cl) * JD + jd] = scale * wv.y;
        Ps[((kb + 2) * 16 + cl) * JD + jd] = scale * wv.z;
        Ps[((kb + 3) * 16 + cl) * JD + jd] = scale * wv.w;
    }
    __syncthreads();

    // --- main loop: thread tile 4b x 20jd, packed f32x2 FMAs ---
    int tx = tid & 7, ty = tid >> 3;          // tx -> jd group of 20, ty -> b group of 4
    ull acc[4][10];
#pragma unroll
    for (int a = 0; a < 4; a++)
#pragma unroll
        for (int e = 0; e < 10; e++) acc[a][e] = 0ULL;

#pragma unroll 2
    for (int r = 0; r < RTILE; r++) {
        float4 xv = *reinterpret_cast<const float4*>(Xs + r * XSTR + ty * 4);
        ull xd[4] = {pack2(xv.x), pack2(xv.y), pack2(xv.z), pack2(xv.w)};
        const ulonglong2* pr =
            reinterpret_cast<const ulonglong2*>(Ps + r * JD + tx * 20);
        ulonglong2 p0 = pr[0], p1 = pr[1], p2 = pr[2], p3 = pr[3], p4 = pr[4];
        ull p[10] = {p0.x, p0.y, p1.x, p1.y, p2.x, p2.y, p3.x, p3.y, p4.x, p4.y};
#pragma unroll
        for (int a = 0; a < 4; a++)
#pragma unroll
            for (int e = 0; e < 10; e++) fma2(acc[a][e], xd[a], p[e]);
    }
    __syncthreads();

    // --- stage output tile, then coalesced float4 store ---
    float* Os = Ps;
#pragma unroll
    for (int a = 0; a < 4; a++) {
        ull* orow = reinterpret_cast<ull*>(Os + (ty * 4 + a) * JD + tx * 20);
#pragma unroll
        for (int e = 0; e < 10; e++) orow[e] = acc[a][e];
    }
    __syncthreads();

    float* dst = g_spart + (size_t)chunk * (BB * JD) + (size_t)b0 * JD;
    for (int i = tid; i < BTILE * JD / 4; i += 256)
        reinterpret_cast<float4*>(dst)[i] = reinterpret_cast<const float4*>(Os)[i];
}

// ---------------------------------------------------------------------------
// Kernel C: reduce split-K partials + squash -> v ; final iter writes d_out
// grid = BB, block = 160
// ---------------------------------------------------------------------------
__global__ void __launch_bounds__(JD) kernC(float* __restrict__ out) {
    int b = blockIdx.x, t = threadIdx.x;
    float s = 1e-5f;                          // ref adds 1e-5 BEFORE magnitudes
    const float* sp = g_spart + (size_t)b * JD + t;
#pragma unroll 8
    for (int ch = 0; ch < NCHUNK; ch++)
        s += sp[(size_t)ch * (BB * JD)];

    __shared__ float sv[JD];
    sv[t] = s;
    __syncthreads();

    int j = t >> 4;
    float mag = 0.f;
#pragma unroll
    for (int d2 = 0; d2 < DD; d2++) { float u = sv[j * 16 + d2]; mag += u * u; }
    float v = s * (mag / ((1.f + mag) * sqrtf(mag)));

    g_v[(size_t)b * JD + t] = v;
    if (out) out[(size_t)b * JD + t] = v;     // (B,J,D,1) same linearization
}

// ---------------------------------------------------------------------------
// Kernel D: GEMM2  G[(k,c),(j,d)] = sum_b x[b,k,c] v[b,j,d] (per b-half),
// contract with W into agreement, atomically update b_ij.
// grid = (NCHUNK, NBT), block = 256
// smem: Xs[b][XSTR] (r contiguous), Vs[b][160] (reused as G tile)
// ---------------------------------------------------------------------------
__global__ void __launch_bounds__(256, 1) kernD(const float* __restrict__ x,
                                                const float* __restrict__ W) {
    extern __shared__ float sm[];
    float* Xs = sm;                    // BTILE * XSTR  [b][r]
    float* Vs = sm + BTILE * XSTR;     // BTILE * JD

    int chunk = blockIdx.x;
    int c0 = chunk * CCHUNK;
    int b0 = blockIdx.y * BTILE;
    int tid = threadIdx.x;

    for (int i = tid; i < BTILE * JD / 4; i += 256)
        reinterpret_cast<float4*>(Vs)[i] =
            *reinterpret_cast<const float4*>(g_v + (size_t)b0 * JD + i * 4);

    // X tile [b][r]: contiguous float4 stores (r = k*16 + cl is 4-consecutive)
    for (int i = tid; i < BTILE * RTILE / 4; i += 256) {
        int b = i >> 5, rq = i & 31;
        int k = rq >> 2, clq = (rq & 3) * 4;
        float4 xv = *reinterpret_cast<const float4*>(
            x + (size_t)(b0 + b) * (KIN * CC) + k * CC + c0 + clq);
        *reinterpret_cast<float4*>(Xs + b * XSTR + k * 16 + clq) = xv;
    }
    __syncthreads();

    int tx = tid & 7, ty = tid >> 3;   // tx -> jd group of 20, ty -> r group of 4
    ull acc[4][10];
#pragma unroll
    for (int a = 0; a < 4; a++)
#pragma unroll
        for (int e = 0; e < 10; e++) acc[a][e] = 0ULL;

#pragma unroll 2
    for (int b = 0; b < BTILE; b++) {
        float4 xv = *reinterpret_cast<const float4*>(Xs + b * XSTR + ty * 4);
        ull xd[4] = {pack2(xv.x), pack2(xv.y), pack2(xv.z), pack2(xv.w)};
        const ulonglong2* vr =
            reinterpret_cast<const ulonglong2*>(Vs + b * JD + tx * 20);
        ulonglong2 v0 = vr[0], v1 = vr[1], v2 = vr[2], v3 = vr[3], v4 = vr[4];
        ull vp[10] = {v0.x, v0.y, v1.x, v1.y, v2.x, v2.y, v3.x, v3.y, v4.x, v4.y};
#pragma unroll
        for (int a = 0; a < 4; a++)
#pragma unroll
            for (int e = 0; e < 10; e++) fma2(acc[a][e], xd[a], vp[e]);
    }
    __syncthreads();

    // park G tile (reuse Vs)
    float* Gs = Vs;
#pragma unroll
    for (int a = 0; a < 4; a++) {
        ull* grow = reinterpret_cast<ull*>(Gs + (ty * 4 + a) * JD + tx * 20);
#pragma unroll
        for (int e = 0; e < 10; e++) grow[e] = acc[a][e];
    }
    __syncthreads();

    // agreement[c,j] = sum_{d,k} W[c,j,d,k] * G[(k,cl)][j*16+d]
    if (tid < CCHUNK * JJ) {
        int cl = tid / JJ, j = tid - cl * JJ;
        int c = c0 + cl;
        const float* wr = W + (size_t)c * (JJ * DD * KIN) + (size_t)j * (DD * KIN);
        float ag = 0.f;
#pragma unroll
        for (int d2 = 0; d2 < DD; d2++)
#pragma unroll
            for (int k = 0; k < KIN; k++)
                ag = fmaf(wr[d2 * KIN + k], Gs[(k * 16 + cl) * JD + j * 16 + d2], ag);
        atomicAdd(&g_b[c * JJ + j], ag);
    }
}

// ---------------------------------------------------------------------------
// Host launcher (graph-capturable)
// ---------------------------------------------------------------------------
extern "C" void kernel_launch(void* const* d_in, const int* in_sizes, int n_in,
                              void* d_out, int out_size) {
    const float* x = (const float*)d_in[0];
    const float* W = (const float*)d_in[1];
    if (in_sizes[0] != BB * KIN * CC) {  // defensive mapping by element count
        x = (const float*)d_in[1];
        W = (const float*)d_in[0];
    }

    const int SMEM_B = (RTILE * XSTR + RTILE * JD + CCHUNK * JJ) * 4;  // 150144
    const int SMEM_D = (BTILE * XSTR + BTILE * JD) * 4;                // 149504
    cudaFuncSetAttribute(kernB, cudaFuncAttributeMaxDynamicSharedMemorySize, SMEM_B);
    cudaFuncSetAttribute(kernD, cudaFuncAttributeMaxDynamicSharedMemorySize, SMEM_D);

    void* pb = nullptr;
    cudaGetSymbolAddress(&pb, g_b);
    cudaMemsetAsync(pb, 0, CC * JJ * sizeof(float));   // b_ij = 0 each call

    dim3 gG(NCHUNK, NBT);
    for (int it = 0; it < 4; it++) {
        kernB<<<gG, 256, SMEM_B>>>(x, W);                      // softmax+P+GEMM1
        kernC<<<BB, JD>>>(it == 3 ? (float*)d_out : nullptr);  // reduce + squash
        if (it < 3)                                            // iter-4 agreement dead
            kernD<<<gG, 256, SMEM_D>>>(x, W);                  // GEMM2 + agreement
    }
}

// round 3
// speedup vs baseline: 1.7354x; 1.0906x over previous
#include <cuda_runtime.h>
#include <math.h>

// Problem constants
#define BB   256           // batch
#define KIN  8             // in_units
#define CC   1152          // in_channels
#define JJ   10            // num_units
#define DD   16            // unit_size
#define JD   160           // JJ*DD
#define XKC  (KIN*CC)      // 9216

#define CB   16            // capsules per chunk
#define NCHB (CC/CB)       // 72
#define RB   (CB*KIN)      // 128 reduction rows per chunk
#define BTB  128           // batch tile
#define XSTR 132           // padded minor stride (16B-aligned, conflict-free)

typedef unsigned long long ull;

// ---------------------------------------------------------------------------
// Scratch (device globals; runtime allocation forbidden)
// ---------------------------------------------------------------------------
__device__ alignas(16) float g_spart[NCHB * BB * JD];  // split-K partials of s
__device__ alignas(16) float g_v[BB * JD];             // v[b][jd]
__device__ alignas(16) float g_b[CC * JJ];             // routing logits

__device__ __forceinline__ ull pack2(float x) {
    ull r; asm("mov.b64 %0, {%1, %1};" : "=l"(r) : "f"(x)); return r;
}
__device__ __forceinline__ void fma2(ull& d, ull a, ull b) {
    asm("fma.rn.f32x2 %0, %1, %2, %0;" : "+l"(d) : "l"(a), "l"(b));
}

// ---------------------------------------------------------------------------
// Kernel B (fused softmax + GEMM1):
//   s_partial[chunk][b][jd] += x[b,k,c] * softmax(b_ij)[c,j] * W[c,j,d,k]
// grid = (72, 2), block = 512; smem: Xs[128r][132b] + Ps[128r][160jd] + cs[160]
// thread tile: 4b x 10jd (tx in [0,16) -> jd, ty in [0,32) -> b)
// ---------------------------------------------------------------------------
__global__ void __launch_bounds__(512) kernB(const float* __restrict__ x,
                                             const float* __restrict__ W) {
    extern __shared__ float sm[];
    float* Xs = sm;                     // RB * XSTR   [r][b]
    float* Ps = sm + RB * XSTR;         // RB * JD     [r][jd]
    float* cs = Ps + RB * JD;           // CB * JJ = 160

    int c0 = blockIdx.x * CB;
    int b0 = blockIdx.y * BTB;
    int tid = threadIdx.x;

    // per-capsule softmax over J
    if (tid < CB * JJ) {
        int cl = tid / JJ, j = tid - cl * JJ;
        const float* br = g_b + (size_t)(c0 + cl) * JJ;
        float bv[JJ], mx = -1e30f;
#pragma unroll
        for (int q = 0; q < JJ; q++) { bv[q] = br[q]; mx = fmaxf(mx, bv[q]); }
        float sum = 0.f;
#pragma unroll
        for (int q = 0; q < JJ; q++) { bv[q] = expf(bv[q] - mx); sum += bv[q]; }
        cs[tid] = bv[j] / sum;
    }

    // X tile, transposed to [r][b] (conflict-free STS.128, stride 132)
    for (int i = tid; i < RB * (BTB / 4); i += 512) {
        int r = i & 127, bq = i >> 7;
        int k = r >> 4, cl = r & 15;
        const float* xp = x + (size_t)(b0 + bq * 4) * XKC + k * CC + c0 + cl;
        float4 v;
        v.x = xp[0]; v.y = xp[XKC]; v.z = xp[2 * XKC]; v.w = xp[3 * XKC];
        *reinterpret_cast<float4*>(Xs + r * XSTR + bq * 4) = v;
    }
    __syncthreads();   // cs ready before scaling W

    // P tile: Ps[k*16+cl][jd] = cs[cl][jd>>4] * W[c0+cl, jd, k]
    for (int i = tid; i < RB * JD / 4; i += 512) {
        int cl = i / 320, rem = i - cl * 320;
        int jd = rem >> 1, k4 = rem & 1;
        float sc = cs[cl * JJ + (jd >> 4)];
        float4 wv = *reinterpret_cast<const float4*>(
            W + (size_t)(c0 + cl) * 1280 + jd * 8 + k4 * 4);
        int kb = k4 * 4;
        Ps[((kb + 0) * 16 + cl) * JD + jd] = sc * wv.x;
        Ps[((kb + 1) * 16 + cl) * JD + jd] = sc * wv.y;
        Ps[((kb + 2) * 16 + cl) * JD + jd] = sc * wv.z;
        Ps[((kb + 3) * 16 + cl) * JD + jd] = sc * wv.w;
    }
    __syncthreads();

    int tx = tid & 15, ty = tid >> 4;
    ull acc[4][5];
#pragma unroll
    for (int a = 0; a < 4; a++)
#pragma unroll
        for (int e = 0; e < 5; e++) acc[a][e] = 0ULL;

    const float* xp = Xs + ty * 4;
    const ull*   pp = reinterpret_cast<const ull*>(Ps + tx * 10);
#pragma unroll 2
    for (int r = 0; r < RB; r++) {
        float4 xv = *reinterpret_cast<const float4*>(xp); xp += XSTR;
        ull p[5];
#pragma unroll
        for (int e = 0; e < 5; e++) p[e] = pp[e];
        pp += JD / 2;
        ull xd[4] = {pack2(xv.x), pack2(xv.y), pack2(xv.z), pack2(xv.w)};
#pragma unroll
        for (int a = 0; a < 4; a++)
#pragma unroll
            for (int e = 0; e < 5; e++) fma2(acc[a][e], xd[a], p[e]);
    }

    // direct global store of the 4x10 fragment (8B-aligned STG.64)
    float* dst = g_spart + (size_t)blockIdx.x * (BB * JD)
               + (size_t)(b0 + ty * 4) * JD + tx * 10;
#pragma unroll
    for (int a = 0; a < 4; a++) {
        ull* o = reinterpret_cast<ull*>(dst + a * JD);
#pragma unroll
        for (int e = 0; e < 5; e++) o[e] = acc[a][e];
    }
}

// ---------------------------------------------------------------------------
// Kernel C: reduce split-K partials + squash -> v ; final iter writes d_out
// grid = 80, block = 512 (one thread per (b,jd) element; shfl over 16 d-lanes)
// ---------------------------------------------------------------------------
__global__ void __launch_bounds__(512) kernC(float* __restrict__ out) {
    int idx = blockIdx.x * 512 + threadIdx.x;   // b*160 + j*16 + d
    float s = 1e-5f;                            // ref adds 1e-5 BEFORE magnitudes
    const float* sp = g_spart + idx;
#pragma unroll 8
    for (int ch = 0; ch < NCHB; ch++)
        s += sp[(size_t)ch * (BB * JD)];

    float mag = s * s;
#pragma unroll
    for (int off = 8; off; off >>= 1)
        mag += __shfl_xor_sync(0xffffffffu, mag, off, 16);

    float v = s * (mag / ((1.f + mag) * sqrtf(mag)));
    g_v[idx] = v;
    if (out) out[idx] = v;                      // (B,J,D,1) same linearization
}

// ---------------------------------------------------------------------------
// Kernel D: GEMM2  G[(k,c),(j,d)] = sum_b x[b,k,c] v[b,j,d] (per b-half),
// then contract with W into agreement, atomically update b_ij.
// grid = (72, 2), block = 512; smem: Xs[128b][132r] + Vs[128b][160jd]
// thread tile: 4r x 10jd
// ---------------------------------------------------------------------------
__global__ void __launch_bounds__(512) kernD(const float* __restrict__ x,
                                             const float* __restrict__ W) {
    extern __shared__ float sm[];
    float* Xs = sm;                     // BTB * XSTR  [b][r]
    float* Vs = sm + BTB * XSTR;        // BTB * JD

    int c0 = blockIdx.x * CB;
    int b0 = blockIdx.y * BTB;
    int tid = threadIdx.x;

    for (int i = tid; i < BTB * JD / 4; i += 512)
        reinterpret_cast<float4*>(Vs)[i] =
            *reinterpret_cast<const float4*>(g_v + (size_t)b0 * JD + i * 4);

    for (int i = tid; i < BTB * (RB / 4); i += 512) {
        int b = i >> 5, rq = i & 31;
        int k = rq >> 2, cl4 = (rq & 3) * 4;
        float4 xv = *reinterpret_cast<const float4*>(
            x + (size_t)(b0 + b) * XKC + k * CC + c0 + cl4);
        *reinterpret_cast<float4*>(Xs + b * XSTR + k * 16 + cl4) = xv;
    }
    __syncthreads();

    int tx = tid & 15, ty = tid >> 4;
    ull acc[4][5];
#pragma unroll
    for (int a = 0; a < 4; a++)
#pragma unroll
        for (int e = 0; e < 5; e++) acc[a][e] = 0ULL;

    const float* xp = Xs + ty * 4;
    const ull*   vp = reinterpret_cast<const ull*>(Vs + tx * 10);
#pragma unroll 2
    for (int b = 0; b < BTB; b++) {
        float4 xv = *reinterpret_cast<const float4*>(xp); xp += XSTR;
        ull v[5];
#pragma unroll
        for (int e = 0; e < 5; e++) v[e] = vp[e];
        vp += JD / 2;
        ull xd[4] = {pack2(xv.x), pack2(xv.y), pack2(xv.z), pack2(xv.w)};
#pragma unroll
        for (int a = 0; a < 4; a++)
#pragma unroll
            for (int e = 0; e < 5; e++) fma2(acc[a][e], xd[a], v[e]);
    }
    __syncthreads();

    // stage full G tile (128r x 160jd = 80KB) into reused smem
    float* Gs = sm;
#pragma unroll
    for (int a = 0; a < 4; a++) {
        ull* grow = reinterpret_cast<ull*>(Gs + (ty * 4 + a) * JD + tx * 10);
#pragma unroll
        for (int e = 0; e < 5; e++) grow[e] = acc[a][e];
    }
    __syncthreads();

    // agreement[c,j] = sum_{k,d} W[c,j,d,k] * G[(k*16+cl)][(j*16+d)]
    if (tid < CB * JJ) {
        int cl = tid / JJ, j = tid - cl * JJ;
        const float* wr = W + (size_t)(c0 + cl) * 1280 + j * 128;
        float ag = 0.f;
#pragma unroll
        for (int k = 0; k < KIN; k++)
#pragma unroll
            for (int d = 0; d < DD; d++)
                ag = fmaf(wr[d * 8 + k], Gs[(k * 16 + cl) * JD + j * 16 + d], ag);
        atomicAdd(&g_b[(c0 + cl) * JJ + j], ag);
    }
}

// ---------------------------------------------------------------------------
// Host launcher (graph-capturable)
// ---------------------------------------------------------------------------
extern "C" void kernel_launch(void* const* d_in, const int* in_sizes, int n_in,
                              void* d_out, int out_size) {
    const float* x = (const float*)d_in[0];
    const float* W = (const float*)d_in[1];
    if (in_sizes[0] != BB * KIN * CC) {   // defensive mapping by element count
        x = (const float*)d_in[1];
        W = (const float*)d_in[0];
    }

    const int SMEM_B = (RB * XSTR + RB * JD + CB * JJ) * 4;   // 150144
    const int SMEM_D = (BTB * XSTR + BTB * JD) * 4;           // 149504
    cudaFuncSetAttribute(kernB, cudaFuncAttributeMaxDynamicSharedMemorySize, SMEM_B);
    cudaFuncSetAttribute(kernD, cudaFuncAttributeMaxDynamicSharedMemorySize, SMEM_D);

    void* pb = nullptr;
    cudaGetSymbolAddress(&pb, g_b);
    cudaMemsetAsync(pb, 0, CC * JJ * sizeof(float));          // b_ij = 0 each call

    dim3 gG(NCHB, 2);
    for (int it = 0; it < 4; it++) {
        kernB<<<gG, 512, SMEM_B>>>(x, W);                       // softmax+P+GEMM1
        kernC<<<(BB * JD) / 512, 512>>>(it == 3 ? (float*)d_out : nullptr);
        if (it < 3)                                             // iter-4 agreement dead
            kernD<<<gG, 512, SMEM_D>>>(x, W);                   // GEMM2 + agreement
    }
}